// round 15
// baseline (speedup 1.0000x reference)
#include <cuda_runtime.h>
#include <cuda_bf16.h>
#include <cstdint>

#define N_ANCH   2000000
#define N_GRP    (N_ANCH / 4)
#define K_SEL    2000
#define OUT_ROWS 1000
#define IMG_SZ   800.0f
#define MIN_SZ   16.0f
#define NMS_TH   0.7f

#define NFINE    4096
#define NCOARSE  65536
#define HI_CAP   262144
#define HI_LO    0.984375f          // 63/64 (known-good config)
#define STAGE_CAP 1024
#define PAIR_CAP  2000000
#define SP_CAP    8192              // sorted outgoing-edge cache
#define SI_CAP    2048              // intra-chunk edge cache
#define NCHUNK   63                 // ceil(2000/32)

#define CTL_FLAG   0
#define CTL_NHI    1
#define CTL_NPAIRS 2

#define PAIR_GX   63
#define PAIR_GY   250

// -------- device scratch (zero-initialized at load; kernels self-clean) ----
__device__ unsigned int       g_hist_fine[NFINE];
__device__ unsigned int       g_hist_coarse[NCOARSE];
__device__ unsigned int       g_ctl[16];
__device__ unsigned long long g_hi[HI_CAP];
__device__ unsigned int       g_keys[N_ANCH];          // fallback only
__device__ float4             g_boxes[K_SEL];
__device__ unsigned char      g_validk[K_SEL];
__device__ unsigned int       g_pairs[PAIR_CAP];

// -------- decode helper (matches reference math) --------
__device__ __forceinline__ float4 decode_box(float4 a, float4 l) {
    float w  = a.z - a.x;
    float h  = a.w - a.y;
    float cx = a.x + 0.5f * w;
    float cy = a.y + 0.5f * h;
    float pcx = cx + l.x * w;
    float pcy = cy + l.y * h;
    float pw  = w * expf(l.z);
    float ph  = h * expf(l.w);
    float x1 = fminf(fmaxf(pcx - 0.5f * pw, 0.0f), IMG_SZ);
    float y1 = fminf(fmaxf(pcy - 0.5f * ph, 0.0f), IMG_SZ);
    float x2 = fminf(fmaxf(pcx + 0.5f * pw, 0.0f), IMG_SZ);
    float y2 = fminf(fmaxf(pcy + 0.5f * ph, 0.0f), IMG_SZ);
    return make_float4(x1, y1, x2, y2);
}

__device__ __forceinline__ bool iou_exact(float4 ba, float4 bb) {
    float xx1 = fmaxf(ba.x, bb.x);
    float yy1 = fmaxf(ba.y, bb.y);
    float xx2 = fminf(ba.z, bb.z);
    float yy2 = fminf(ba.w, bb.w);
    float iw = fmaxf(xx2 - xx1, 0.0f);
    float ih = fmaxf(yy2 - yy1, 0.0f);
    float inter = iw * ih;
    float ai = (ba.z - ba.x) * (ba.w - ba.y);
    float aj = (bb.z - bb.x) * (bb.w - bb.y);
    float u = fmaxf(ai + aj - inter, 1e-9f);
    return (inter / u > NMS_TH);
}

// -------- K1: score scan (phase 1) + block-parallel hit decode (phase 2) ---
__global__ void __launch_bounds__(256) k_scan(const float4* __restrict__ locs,
                                              const float4* __restrict__ scores4,
                                              const float4* __restrict__ anchors) {
    __shared__ unsigned long long stage[STAGE_CAP];
    __shared__ int s_cnt, s_cnt2;
    __shared__ unsigned int s_base;
    int t = threadIdx.x;
    if (t == 0) { s_cnt = 0; s_cnt2 = 0; }
    __syncthreads();

    int g0 = blockIdx.x * 512 + t;
    int g1 = g0 + 256;
    float4 sA = (g0 < N_GRP) ? scores4[g0] : make_float4(0.f, 0.f, 0.f, 0.f);
    float4 sB = (g1 < N_GRP) ? scores4[g1] : make_float4(0.f, 0.f, 0.f, 0.f);
    #pragma unroll
    for (int half = 0; half < 2; half++) {
        int g = (half == 0) ? g0 : g1;
        float4 s4 = (half == 0) ? sA : sB;
        if (g >= N_GRP) continue;
        #pragma unroll
        for (int c = 0; c < 4; c++) {
            float s = (c == 0) ? s4.x : (c == 1) ? s4.y : (c == 2) ? s4.z : s4.w;
            if (s >= HI_LO) {
                unsigned int i = (unsigned)(4 * g + c);
                unsigned int key = __float_as_uint(s) + 1u;
                int p = atomicAdd(&s_cnt, 1);
                if (p < STAGE_CAP)
                    stage[p] = ((unsigned long long)key << 32) | (unsigned int)(~i);
                else
                    g_ctl[CTL_FLAG] = 1u;
            }
        }
    }
    __syncthreads();
    int cnt = s_cnt;
    if (cnt > STAGE_CAP) cnt = STAGE_CAP;

    // phase 2: parallel decode of staged hits; compact valid in place
    for (int base = 0; base < cnt; base += 256) {
        unsigned long long v = 0ULL;
        bool valid = false;
        int fbin = 0;
        int p = base + t;
        if (p < cnt) {
            v = stage[p];
            unsigned int i = ~(unsigned int)(v & 0xFFFFFFFFu);
            float4 d = decode_box(anchors[i], locs[i]);
            valid = (d.z - d.x >= MIN_SZ) && (d.w - d.y >= MIN_SZ);
            if (valid) {
                float s = __uint_as_float((unsigned int)(v >> 32) - 1u);
                int f = (int)(s * 262144.0f) - 258048;
                if (f > NFINE - 1) f = NFINE - 1;
                float lo = (float)(258048 + f) * (1.0f / 262144.0f);
                if (s < lo) f--;
                if (f < 0) valid = false; else fbin = f;
            }
        }
        __syncthreads();
        if (valid) {
            atomicAdd(&g_hist_fine[fbin], 1u);
            stage[atomicAdd(&s_cnt2, 1)] = v;
        }
    }
    __syncthreads();
    int cnt2 = s_cnt2;
    if (t == 0 && cnt2 > 0)
        s_base = atomicAdd(&g_ctl[CTL_NHI], (unsigned)cnt2);
    __syncthreads();
    if (cnt2 > 0) {
        unsigned int b = s_base;
        for (int p = t; p < cnt2; p += 256)
            if (b + p < (unsigned)HI_CAP) g_hi[b + p] = stage[p];
            else g_ctl[CTL_FLAG] = 1u;
    }
}

// -------- fallback path (adversarial data only): exact full-range select ----
__device__ void fb_path(const float4* __restrict__ locs,
                        const float*  __restrict__ scores,
                        const float4* __restrict__ anchors,
                        unsigned int* A, unsigned int* B,
                        unsigned long long* sv, int* s_nc, unsigned int* s_T) {
    int t = threadIdx.x;
    for (int i = t; i < N_ANCH; i += 1024) {
        float4 d = decode_box(anchors[i], locs[i]);
        float  s = scores[i];
        bool valid = (d.z - d.x >= MIN_SZ) && (d.w - d.y >= MIN_SZ);
        unsigned int key = valid ? (__float_as_uint(s) + 1u) : 0u;
        g_keys[i] = key;
        if (key) {
            float sc = fmaxf(s, 0.0f);
            int b = (int)(sc * 65536.0f);
            if (b > NCOARSE - 1) b = NCOARSE - 1;
            float lo = (float)b * (1.0f / 65536.0f);
            if (sc < lo) b--;
            if (b < 0) b = 0;
            atomicAdd(&g_hist_coarse[b], 1u);
        }
    }
    __syncthreads();
    const unsigned int* h = &g_hist_coarse[t * 64];
    unsigned int s = 0;
    #pragma unroll 8
    for (int i = 0; i < 64; i++) s += h[i];
    A[t] = s;
    __syncthreads();
    unsigned int* src = A; unsigned int* dst = B;
    for (int d = 1; d < 1024; d <<= 1) {
        dst[t] = src[t] + (t + d < 1024 ? src[t + d] : 0u);
        __syncthreads();
        unsigned int* tmp = src; src = dst; dst = tmp;
    }
    unsigned int total = src[0];
    if (t == 0) *s_T = 1u;
    __syncthreads();
    if (total >= (unsigned)K_SEL) {
        unsigned int suf  = src[t];
        unsigned int sufN = (t == 1023) ? 0u : src[t + 1];
        if (suf >= (unsigned)K_SEL && sufN < (unsigned)K_SEL) {
            unsigned int running = sufN;
            for (int i = 63; i >= 0; i--) {
                running += h[i];
                if (running >= (unsigned)K_SEL) {
                    *s_T = __float_as_uint((float)(t * 64 + i) * (1.0f / 65536.0f)) + 1u;
                    break;
                }
            }
        }
    }
    if (t == 0) *s_nc = 0;
    __syncthreads();
    unsigned int T = *s_T;
    for (int i = t; i < N_ANCH; i += 1024) {
        unsigned int key = g_keys[i];
        if (key >= T) {
            int p = atomicAdd(s_nc, 1);
            if (p < 4096)
                sv[p] = ((unsigned long long)key << 32) | (unsigned int)(~(unsigned)i);
        }
    }
    __syncthreads();
    int nc = *s_nc; if (nc > 4096) nc = 4096;
    int S = (nc <= 2048) ? 2048 : 4096;
    for (int i = nc + t; i < S; i += 1024) sv[i] = 0ULL;
    __syncthreads();
    int half = S >> 1;
    for (int k = 2; k <= S; k <<= 1) {
        for (int j = k >> 1; j > 0; j >>= 1) {
            for (int w = t; w < half; w += 1024) {
                int i = ((w & ~(j - 1)) << 1) | (w & (j - 1));
                int p = i | j;
                unsigned long long va = sv[i], vb = sv[p];
                bool up = ((i & k) == 0);
                if (up ? (va < vb) : (va > vb)) { sv[i] = vb; sv[p] = va; }
            }
            __syncthreads();
        }
    }
    for (int r = t; r < K_SEL; r += 1024) {
        unsigned long long v = sv[r];
        unsigned int key = (unsigned int)(v >> 32);
        unsigned int idx = ~(unsigned int)(v & 0xFFFFFFFFu);
        g_validk[r] = (key != 0u) ? 1 : 0;
        float4 box = make_float4(0.f, 0.f, 0.f, 0.f);
        if (key != 0u) box = decode_box(anchors[idx], locs[idx]);
        g_boxes[r] = box;
    }
    __syncthreads();
    for (int i = t; i < NCOARSE; i += 1024) g_hist_coarse[i] = 0u;
}

// -------- K2: fused select + collect + sort + boxes (+ inline fallback) ----
__global__ void k_top(const float4* __restrict__ locs,
                      const float*  __restrict__ scores,
                      const float4* __restrict__ anchors) {
    __shared__ unsigned int A[1024], B[1024];
    __shared__ unsigned long long sv[4096];
    __shared__ int s_nc;
    __shared__ unsigned int s_T;
    int t = threadIdx.x;

    unsigned int* h = &g_hist_fine[t * 4];
    unsigned int h0 = h[0], h1 = h[1], h2 = h[2], h3 = h[3];
    h[0] = 0u; h[1] = 0u; h[2] = 0u; h[3] = 0u;        // self-clean
    A[t] = h0 + h1 + h2 + h3;
    __syncthreads();

    unsigned int* src = A; unsigned int* dst = B;
    for (int d = 1; d < 1024; d <<= 1) {
        dst[t] = src[t] + (t + d < 1024 ? src[t + d] : 0u);
        __syncthreads();
        unsigned int* tmp = src; src = dst; dst = tmp;
    }
    unsigned int total = src[0];
    unsigned int nhi   = g_ctl[CTL_NHI];
    bool fb = (g_ctl[CTL_FLAG] != 0u) || (total < (unsigned)K_SEL) || (nhi > (unsigned)HI_CAP);

    if (!fb) {
        unsigned int suf  = src[t];
        unsigned int sufN = (t == 1023) ? 0u : src[t + 1];
        if (suf >= (unsigned)K_SEL && sufN < (unsigned)K_SEL) {
            unsigned int running = sufN;
            unsigned int hv[4] = {h0, h1, h2, h3};
            for (int i = 3; i >= 0; i--) {
                running += hv[i];
                if (running >= (unsigned)K_SEL) {
                    s_T = __float_as_uint((float)(258048 + t * 4 + i) * (1.0f / 262144.0f)) + 1u;
                    break;
                }
            }
        }
        if (t == 0) s_nc = 0;
        __syncthreads();
        unsigned int T = s_T;
        for (int i = t; i < (int)nhi; i += 1024) {
            unsigned long long v = g_hi[i];
            if ((unsigned int)(v >> 32) >= T) {
                int p = atomicAdd(&s_nc, 1);
                if (p < 4096) sv[p] = v;
            }
        }
        __syncthreads();
        if (s_nc > 4096) fb = true;
    }

    if (fb) {
        if (t == 0) g_ctl[CTL_FLAG] = 1u;
        __syncthreads();
        fb_path(locs, scores, anchors, A, B, sv, &s_nc, &s_T);
        return;
    }

    int nc = s_nc;
    int S = (nc <= 2048) ? 2048 : 4096;
    for (int i = nc + t; i < S; i += 1024) sv[i] = 0ULL;
    __syncthreads();
    int half = S >> 1;
    for (int k = 2; k <= S; k <<= 1) {
        for (int j = k >> 1; j > 0; j >>= 1) {
            for (int w = t; w < half; w += 1024) {
                int i = ((w & ~(j - 1)) << 1) | (w & (j - 1));
                int p = i | j;
                unsigned long long va = sv[i], vb = sv[p];
                bool up = ((i & k) == 0);
                if (up ? (va < vb) : (va > vb)) { sv[i] = vb; sv[p] = va; }
            }
            __syncthreads();
        }
    }
    for (int r = t; r < K_SEL; r += 1024) {
        unsigned long long v = sv[r];
        unsigned int key = (unsigned int)(v >> 32);
        unsigned int idx = ~(unsigned int)(v & 0xFFFFFFFFu);
        g_validk[r] = (key != 0u) ? 1 : 0;
        float4 box = make_float4(0.f, 0.f, 0.f, 0.f);
        if (key != 0u) box = decode_box(anchors[idx], locs[idx]);
        g_boxes[r] = box;
    }
}

// -------- K3: flat candidate-pair extraction (NO division, no smem) --------
__global__ void __launch_bounds__(256) k_pairs() {
    int ic = blockIdx.x;                 // 32 i's
    int jc = blockIdx.y;                 // 8 j's
    if (ic * 32 >= jc * 8 + 8) return;
    int lane = threadIdx.x & 31;
    int w    = threadIdx.x >> 5;
    int i = ic * 32 + lane;
    int j = jc * 8 + w;
    bool hit = false;
    if (i < j && j < K_SEL) {
        float4 ba = g_boxes[i];
        float4 bb = g_boxes[j];
        float xx1 = fmaxf(ba.x, bb.x);
        float yy1 = fmaxf(ba.y, bb.y);
        float xx2 = fminf(ba.z, bb.z);
        float yy2 = fminf(ba.w, bb.w);
        float iw = fmaxf(xx2 - xx1, 0.0f);
        float ih = fmaxf(yy2 - yy1, 0.0f);
        float inter = iw * ih;
        float ai = (ba.z - ba.x) * (ba.w - ba.y);
        float aj = (bb.z - bb.x) * (bb.w - bb.y);
        float u = fmaxf(ai + aj - inter, 1e-9f);
        hit = (inter > 0.699f * u);      // conservative, division-free
    }
    unsigned int mask = __ballot_sync(0xFFFFFFFFu, hit);
    if (mask) {
        int leader = __ffs(mask) - 1;
        unsigned int basep = 0;
        if (lane == leader)
            basep = atomicAdd(&g_ctl[CTL_NPAIRS], (unsigned)__popc(mask));
        basep = __shfl_sync(0xFFFFFFFFu, basep, leader);
        if (hit) {
            int rank = __popc(mask & ((1u << lane) - 1u));
            unsigned int pos = basep + rank;
            if (pos < (unsigned)PAIR_CAP)
                g_pairs[pos] = ((unsigned)i << 11) | (unsigned)j;
        }
    }
}

// -------- K4: exact verify + chunked Gauss-Seidel sweep + compact + output -
__global__ void __launch_bounds__(1024) k_resolve(float* __restrict__ outf) {
    __shared__ unsigned int spo[SP_CAP];     // 32 KB outgoing edges, chunk-sorted
    __shared__ unsigned int spi[SI_CAP];     // 8 KB intra-chunk edges
    __shared__ unsigned int cnt[NCHUNK + 1], off[NCHUNK + 1], off2[NCHUNK + 1];
    __shared__ unsigned int vw[64], kw[64], sup[64], pref[64];
    __shared__ int s_ni, s_ovf, s_changed;

    int t = threadIdx.x;
    int lane = t & 31;
    int warp = t >> 5;
    int np = (int)g_ctl[CTL_NPAIRS];
    if (np > PAIR_CAP) np = PAIR_CAP;

    if (t <= NCHUNK) { cnt[t] = 0u; }
    if (t == 0) { s_ni = 0; s_ovf = (np > SP_CAP) ? 1 : 0; }
    __syncthreads();

    // ---- pass 1: exact verify (divisions), count outgoing per chunk ----
    if (!s_ovf) {
        for (int p = t; p < np; p += 1024) {
            unsigned int pr = g_pairs[p];
            int i = (int)(pr >> 11), j = (int)(pr & 2047u);
            if (iou_exact(g_boxes[i], g_boxes[j])) {
                if ((i >> 5) == (j >> 5)) {
                    if (atomicAdd(&s_ni, 1) >= SI_CAP) s_ovf = 1;
                } else {
                    atomicAdd(&cnt[i >> 5], 1u);
                }
            }
        }
    }
    // build valid/keep bitmask: 32 warps cover 64 words
    for (int wd = warp; wd < 64; wd += 32) {
        int j = wd * 32 + lane;
        unsigned char v = (j < K_SEL) ? g_validk[j] : (unsigned char)0;
        unsigned int m = __ballot_sync(0xFFFFFFFFu, v != 0);
        if (lane == 0) { vw[wd] = m; kw[wd] = m; }
    }
    __syncthreads();

    if (!s_ovf) {
        // ---- prefix offsets (lane0 serial over 63 values) + scatter ----
        if (t == 0) {
            unsigned int run = 0;
            for (int c = 0; c < NCHUNK; c++) { off[c] = run; off2[c] = run; run += cnt[c]; }
            off[NCHUNK] = run;
            s_ni = 0;                                   // reuse as intra append ctr
        }
        __syncthreads();
        // pass 2: recompute verify, scatter
        for (int p = t; p < np; p += 1024) {
            unsigned int pr = g_pairs[p];
            int i = (int)(pr >> 11), j = (int)(pr & 2047u);
            if (iou_exact(g_boxes[i], g_boxes[j])) {
                if ((i >> 5) == (j >> 5)) {
                    int q = atomicAdd(&s_ni, 1);
                    if (q < SI_CAP) spi[q] = pr;
                } else {
                    spo[atomicAdd(&off2[i >> 5], 1u)] = pr;
                }
            }
        }
        __syncthreads();
        int nI = s_ni; if (nI > SI_CAP) nI = SI_CAP;

        // ---- single-warp deterministic chunk sweep (exact greedy NMS) ----
        if (warp == 0) {
            for (int c = 0; c < NCHUNK; c++) {
                // intra-chunk: bit-serial by lane 0 (rare)
                bool has = false;
                for (int q = lane; q < nI; q += 32)
                    if ((spi[q] >> 16) == (unsigned)c) has = true;
                unsigned int anym = __ballot_sync(0xFFFFFFFFu, has);
                if (anym && lane == 0) {
                    for (int b = 0; b < 32; b++) {
                        int i = c * 32 + b;
                        if ((kw[c] >> b) & 1u) {
                            for (int q = 0; q < nI; q++) {
                                unsigned int ee = spi[q];
                                if ((int)(ee >> 11) == i) {
                                    int j = (int)(ee & 2047u);
                                    kw[j >> 5] &= ~(1u << (j & 31));
                                }
                            }
                        }
                    }
                }
                __syncwarp();
                // outgoing: lane-parallel (chunk-c bits are final)
                int beg = (int)off[c], end = (int)off[c + 1];
                for (int p = beg + lane; p < end; p += 32) {
                    unsigned int e = spo[p];
                    int i = (int)(e >> 11), j = (int)(e & 2047u);
                    if ((kw[i >> 5] >> (i & 31)) & 1u)
                        atomicAnd(&kw[j >> 5], ~(1u << (j & 31)));
                }
                __syncwarp();
            }
        }
        __syncthreads();
    } else {
        // ---- overflow fallback: mark rejects, global bitmask Jacobi ----
        __syncthreads();
        for (int p = t; p < np; p += 1024) {
            unsigned int pr = g_pairs[p];
            int i = (int)(pr >> 11), j = (int)(pr & 2047u);
            if (!iou_exact(g_boxes[i], g_boxes[j])) g_pairs[p] = 0xFFFFFFFFu;
        }
        __syncthreads();
        for (int it = 0; it <= K_SEL; ++it) {
            if (t < 64) sup[t] = 0u;
            if (t == 0) s_changed = 0;
            __syncthreads();
            for (int p = t; p < np; p += 1024) {
                unsigned int pr = g_pairs[p];
                if (pr == 0xFFFFFFFFu) continue;
                int i = (int)(pr >> 11), j = (int)(pr & 2047u);
                if ((kw[i >> 5] >> (i & 31)) & 1u)
                    atomicOr(&sup[j >> 5], 1u << (j & 31));
            }
            __syncthreads();
            if (t < 64) {
                unsigned int nw = vw[t] & ~sup[t];
                if (nw != kw[t]) { kw[t] = nw; s_changed = 1; }
            }
            __syncthreads();
            int done = (s_changed == 0);
            __syncthreads();
            if (done) break;
        }
    }

    // ---- popcount prefix (warp 0) ----
    if (warp == 0) {
        unsigned int a = __popc(kw[lane]);
        unsigned int b = __popc(kw[lane + 32]);
        unsigned int ia = a;
        #pragma unroll
        for (int d = 1; d < 32; d <<= 1) {
            unsigned int v = __shfl_up_sync(0xFFFFFFFFu, ia, d);
            if (lane >= d) ia += v;
        }
        unsigned int totalA = __shfl_sync(0xFFFFFFFFu, ia, 31);
        unsigned int ib = b;
        #pragma unroll
        for (int d = 1; d < 32; d <<= 1) {
            unsigned int v = __shfl_up_sync(0xFFFFFFFFu, ib, d);
            if (lane >= d) ib += v;
        }
        pref[lane]      = ia - a;
        pref[lane + 32] = totalA + ib - b;
    }
    __syncthreads();

    // ---- output: zero then scatter kept boxes by rank ----
    float4* out4 = (float4*)outf;
    for (int r = t; r < OUT_ROWS; r += 1024)
        out4[r] = make_float4(0.f, 0.f, 0.f, 0.f);
    __syncthreads();
    for (int j = t; j < K_SEL; j += 1024) {
        unsigned int wdm = kw[j >> 5];
        if ((wdm >> (j & 31)) & 1u) {
            int pos = (int)pref[j >> 5] + __popc(wdm & ((1u << (j & 31)) - 1u));
            if (pos < OUT_ROWS) out4[pos] = g_boxes[j];
        }
    }
    __syncthreads();
    if (t < 16) g_ctl[t] = 0u;          // self-clean all control state
}

extern "C" void kernel_launch(void* const* d_in, const int* in_sizes, int n_in,
                              void* d_out, int out_size) {
    const float4* locs    = (const float4*)d_in[0];
    const float*  scores  = (const float*) d_in[1];
    const float4* scores4 = (const float4*)d_in[1];
    const float4* anchors = (const float4*)d_in[2];
    float* out = (float*)d_out;

    k_scan<<<977, 256>>>(locs, scores4, anchors);
    k_top<<<1, 1024>>>(locs, scores, anchors);
    k_pairs<<<dim3(PAIR_GX, PAIR_GY), 256>>>();
    k_resolve<<<1, 1024>>>(out);
}

// round 16
// speedup vs baseline: 1.4080x; 1.4080x over previous
#include <cuda_runtime.h>
#include <cuda_bf16.h>
#include <cstdint>

#define N_ANCH   2000000
#define N_GRP    (N_ANCH / 4)
#define K_SEL    2000
#define OUT_ROWS 1000
#define IMG_SZ   800.0f
#define MIN_SZ   16.0f
#define NMS_TH   0.7f

#define NFINE    4096
#define FOFF     258048             // (63/64) * 262144
#define NCOARSE  65536
#define HI_CAP   262144
#define HI_LO    0.984375f          // 63/64
#define STAGE_CAP 1024
#define PAIR_CAP  2000000

#define CTL_FLAG   0
#define CTL_NHI    1
#define CTL_NPAIRS 2

#define PAIR_GX   63
#define PAIR_GY   250

// -------- device scratch (zero-initialized at load; kernels self-clean) ----
__device__ unsigned int       g_hist_fine[NFINE];
__device__ unsigned int       g_hist_coarse[NCOARSE];
__device__ unsigned int       g_ctl[16];
__device__ unsigned long long g_hi[HI_CAP];
__device__ unsigned int       g_keys[N_ANCH];          // fallback only
__device__ float4             g_boxes[K_SEL];
__device__ unsigned char      g_validk[K_SEL];
__device__ unsigned int       g_pairs[PAIR_CAP];

// -------- decode helper (matches reference math) --------
__device__ __forceinline__ float4 decode_box(float4 a, float4 l) {
    float w  = a.z - a.x;
    float h  = a.w - a.y;
    float cx = a.x + 0.5f * w;
    float cy = a.y + 0.5f * h;
    float pcx = cx + l.x * w;
    float pcy = cy + l.y * h;
    float pw  = w * expf(l.z);
    float ph  = h * expf(l.w);
    float x1 = fminf(fmaxf(pcx - 0.5f * pw, 0.0f), IMG_SZ);
    float y1 = fminf(fmaxf(pcy - 0.5f * ph, 0.0f), IMG_SZ);
    float x2 = fminf(fmaxf(pcx + 0.5f * pw, 0.0f), IMG_SZ);
    float y2 = fminf(fmaxf(pcy + 0.5f * ph, 0.0f), IMG_SZ);
    return make_float4(x1, y1, x2, y2);
}

__device__ __forceinline__ int fine_bin(float s) {
    int f = (int)(s * 262144.0f) - FOFF;
    if (f > NFINE - 1) f = NFINE - 1;
    float lo = (float)(FOFF + f) * (1.0f / 262144.0f);   // exact in fp32
    if (s < lo) f--;
    return f;
}

__device__ __forceinline__ void isort_desc(unsigned long long* a, int n) {
    for (int x = 1; x < n; x++) {
        unsigned long long v = a[x];
        int y = x - 1;
        while (y >= 0 && a[y] < v) { a[y + 1] = a[y]; y--; }
        a[y + 1] = v;
    }
}

// -------- K1: score scan (phase 1) + block-parallel hit decode (phase 2) ---
__global__ void __launch_bounds__(256) k_scan(const float4* __restrict__ locs,
                                              const float4* __restrict__ scores4,
                                              const float4* __restrict__ anchors) {
    __shared__ unsigned long long stage[STAGE_CAP];
    __shared__ int s_cnt, s_cnt2;
    __shared__ unsigned int s_base;
    int t = threadIdx.x;
    if (t == 0) { s_cnt = 0; s_cnt2 = 0; }
    __syncthreads();

    int g0 = blockIdx.x * 512 + t;
    int g1 = g0 + 256;
    float4 sA = (g0 < N_GRP) ? scores4[g0] : make_float4(0.f, 0.f, 0.f, 0.f);
    float4 sB = (g1 < N_GRP) ? scores4[g1] : make_float4(0.f, 0.f, 0.f, 0.f);
    #pragma unroll
    for (int half = 0; half < 2; half++) {
        int g = (half == 0) ? g0 : g1;
        float4 s4 = (half == 0) ? sA : sB;
        if (g >= N_GRP) continue;
        #pragma unroll
        for (int c = 0; c < 4; c++) {
            float s = (c == 0) ? s4.x : (c == 1) ? s4.y : (c == 2) ? s4.z : s4.w;
            if (s >= HI_LO) {
                unsigned int i = (unsigned)(4 * g + c);
                unsigned int key = __float_as_uint(s) + 1u;
                int p = atomicAdd(&s_cnt, 1);
                if (p < STAGE_CAP)
                    stage[p] = ((unsigned long long)key << 32) | (unsigned int)(~i);
                else
                    g_ctl[CTL_FLAG] = 1u;
            }
        }
    }
    __syncthreads();
    int cnt = s_cnt;
    if (cnt > STAGE_CAP) cnt = STAGE_CAP;

    // phase 2: parallel decode of staged hits; compact valid in place
    for (int base = 0; base < cnt; base += 256) {
        unsigned long long v = 0ULL;
        bool valid = false;
        int fbin = 0;
        int p = base + t;
        if (p < cnt) {
            v = stage[p];
            unsigned int i = ~(unsigned int)(v & 0xFFFFFFFFu);
            float4 d = decode_box(anchors[i], locs[i]);
            valid = (d.z - d.x >= MIN_SZ) && (d.w - d.y >= MIN_SZ);
            if (valid) {
                float s = __uint_as_float((unsigned int)(v >> 32) - 1u);
                int f = fine_bin(s);
                if (f < 0) valid = false; else fbin = f;
            }
        }
        __syncthreads();
        if (valid) {
            atomicAdd(&g_hist_fine[fbin], 1u);
            stage[atomicAdd(&s_cnt2, 1)] = v;
        }
    }
    __syncthreads();
    int cnt2 = s_cnt2;
    if (t == 0 && cnt2 > 0)
        s_base = atomicAdd(&g_ctl[CTL_NHI], (unsigned)cnt2);
    __syncthreads();
    if (cnt2 > 0) {
        unsigned int b = s_base;
        for (int p = t; p < cnt2; p += 256)
            if (b + p < (unsigned)HI_CAP) g_hi[b + p] = stage[p];
            else g_ctl[CTL_FLAG] = 1u;
    }
}

// -------- fallback path (adversarial data only): exact full-range select ----
__device__ void fb_path(const float4* __restrict__ locs,
                        const float*  __restrict__ scores,
                        const float4* __restrict__ anchors,
                        unsigned int* A, unsigned int* B,
                        unsigned long long* sv, int* s_nc, unsigned int* s_T) {
    int t = threadIdx.x;
    for (int i = t; i < N_ANCH; i += 1024) {
        float4 d = decode_box(anchors[i], locs[i]);
        float  s = scores[i];
        bool valid = (d.z - d.x >= MIN_SZ) && (d.w - d.y >= MIN_SZ);
        unsigned int key = valid ? (__float_as_uint(s) + 1u) : 0u;
        g_keys[i] = key;
        if (key) {
            float sc = fmaxf(s, 0.0f);
            int b = (int)(sc * 65536.0f);
            if (b > NCOARSE - 1) b = NCOARSE - 1;
            float lo = (float)b * (1.0f / 65536.0f);
            if (sc < lo) b--;
            if (b < 0) b = 0;
            atomicAdd(&g_hist_coarse[b], 1u);
        }
    }
    __syncthreads();
    const unsigned int* h = &g_hist_coarse[t * 64];
    unsigned int s = 0;
    #pragma unroll 8
    for (int i = 0; i < 64; i++) s += h[i];
    A[t] = s;
    __syncthreads();
    unsigned int* src = A; unsigned int* dst = B;
    for (int d = 1; d < 1024; d <<= 1) {
        dst[t] = src[t] + (t + d < 1024 ? src[t + d] : 0u);
        __syncthreads();
        unsigned int* tmp = src; src = dst; dst = tmp;
    }
    unsigned int total = src[0];
    if (t == 0) *s_T = 1u;
    __syncthreads();
    if (total >= (unsigned)K_SEL) {
        unsigned int suf  = src[t];
        unsigned int sufN = (t == 1023) ? 0u : src[t + 1];
        if (suf >= (unsigned)K_SEL && sufN < (unsigned)K_SEL) {
            unsigned int running = sufN;
            for (int i = 63; i >= 0; i--) {
                running += h[i];
                if (running >= (unsigned)K_SEL) {
                    *s_T = __float_as_uint((float)(t * 64 + i) * (1.0f / 65536.0f)) + 1u;
                    break;
                }
            }
        }
    }
    if (t == 0) *s_nc = 0;
    __syncthreads();
    unsigned int T = *s_T;
    for (int i = t; i < N_ANCH; i += 1024) {
        unsigned int key = g_keys[i];
        if (key >= T) {
            int p = atomicAdd(s_nc, 1);
            if (p < 4096)
                sv[p] = ((unsigned long long)key << 32) | (unsigned int)(~(unsigned)i);
        }
    }
    __syncthreads();
    int nc = *s_nc; if (nc > 4096) nc = 4096;
    int S = (nc <= 2048) ? 2048 : 4096;
    for (int i = nc + t; i < S; i += 1024) sv[i] = 0ULL;
    __syncthreads();
    int half = S >> 1;
    for (int k = 2; k <= S; k <<= 1) {
        for (int j = k >> 1; j > 0; j >>= 1) {
            for (int w = t; w < half; w += 1024) {
                int i = ((w & ~(j - 1)) << 1) | (w & (j - 1));
                int p = i | j;
                unsigned long long va = sv[i], vb = sv[p];
                bool up = ((i & k) == 0);
                if (up ? (va < vb) : (va > vb)) { sv[i] = vb; sv[p] = va; }
            }
            __syncthreads();
        }
    }
    for (int r = t; r < K_SEL; r += 1024) {
        unsigned long long v = sv[r];
        unsigned int key = (unsigned int)(v >> 32);
        unsigned int idx = ~(unsigned int)(v & 0xFFFFFFFFu);
        g_validk[r] = (key != 0u) ? 1 : 0;
        float4 box = make_float4(0.f, 0.f, 0.f, 0.f);
        if (key != 0u) box = decode_box(anchors[idx], locs[idx]);
        g_boxes[r] = box;
    }
    __syncthreads();
    for (int i = t; i < NCOARSE; i += 1024) g_hist_coarse[i] = 0u;  // self-clean
}

// -------- K2: select + counting-placement sort + boxes (+ inline fallback) -
__global__ void k_top(const float4* __restrict__ locs,
                      const float*  __restrict__ scores,
                      const float4* __restrict__ anchors) {
    __shared__ unsigned int A[1024], B[1024];
    __shared__ unsigned long long sv[4096];
    __shared__ int s_nc, s_bad;
    __shared__ unsigned int s_T;
    int t = threadIdx.x;

    if (t == 0) s_bad = 0;
    unsigned int* h = &g_hist_fine[t * 4];
    unsigned int h0 = h[0], h1 = h[1], h2 = h[2], h3 = h[3];
    A[t] = h0 + h1 + h2 + h3;
    __syncthreads();

    unsigned int* src = A; unsigned int* dst = B;
    for (int d = 1; d < 1024; d <<= 1) {
        dst[t] = src[t] + (t + d < 1024 ? src[t + d] : 0u);
        __syncthreads();
        unsigned int* tmp = src; src = dst; dst = tmp;
    }
    unsigned int total = src[0];
    unsigned int nhi   = g_ctl[CTL_NHI];
    bool fb = (g_ctl[CTL_FLAG] != 0u) || (total < (unsigned)K_SEL) || (nhi > (unsigned)HI_CAP);

    unsigned int ord0 = 0, ord1 = 0, ord2 = 0, ord3 = 0;
    if (!fb) {
        unsigned int sufAfter = (t == 1023) ? 0u : src[t + 1];
        // bin-level suffix sums (binSuf(f) = # candidates in bins >= f)
        unsigned int bs3 = sufAfter + h3;
        unsigned int bs2 = bs3 + h2;
        unsigned int bs1 = bs2 + h1;
        unsigned int bs0 = bs1 + h0;
        ord0 = bs1; ord1 = bs2; ord2 = bs3; ord3 = sufAfter;   // start offsets
        unsigned int bsA[4]  = {bs0, bs1, bs2, bs3};
        unsigned int bsN[4]  = {bs1, bs2, bs3, sufAfter};
        #pragma unroll
        for (int i = 0; i < 4; i++) {
            if (bsA[i] >= (unsigned)K_SEL && bsN[i] < (unsigned)K_SEL) {
                s_T  = __float_as_uint((float)(FOFF + t * 4 + i) * (1.0f / 262144.0f)) + 1u;
                s_nc = (int)bsA[i];
            }
        }
        // publish start offsets: reuse g_hist_fine as placement counters
        h[0] = ord0; h[1] = ord1; h[2] = ord2; h[3] = ord3;
        __syncthreads();
        int nc = s_nc;
        // giant-bin guard (score-tie attack): insertion sort must stay tiny
        if ((ord0 < (unsigned)nc && h0 > 64u) || (ord1 < (unsigned)nc && h1 > 64u) ||
            (ord2 < (unsigned)nc && h2 > 64u) || (ord3 < (unsigned)nc && h3 > 64u))
            s_bad = 1;
        __syncthreads();
        if (s_bad) {
            h[0] = 0u; h[1] = 0u; h[2] = 0u; h[3] = 0u;
            fb = true;
        } else {
            unsigned int T = s_T;
            for (int i = t; i < (int)nhi; i += 1024) {
                unsigned long long v = g_hi[i];
                unsigned int key = (unsigned int)(v >> 32);
                if (key >= T) {
                    int f = fine_bin(__uint_as_float(key - 1u));
                    unsigned int slot = atomicAdd(&g_hist_fine[f], 1u);
                    if (slot < 4096u) sv[slot] = v;
                }
            }
            __syncthreads();
            h[0] = 0u; h[1] = 0u; h[2] = 0u; h[3] = 0u;   // self-clean counters
            // intra-bin order fix (tiny insertion sorts; full u64 desc)
            if (ord0 < (unsigned)nc && h0 > 1u) isort_desc(&sv[ord0], (int)h0);
            if (ord1 < (unsigned)nc && h1 > 1u) isort_desc(&sv[ord1], (int)h1);
            if (ord2 < (unsigned)nc && h2 > 1u) isort_desc(&sv[ord2], (int)h2);
            if (ord3 < (unsigned)nc && h3 > 1u) isort_desc(&sv[ord3], (int)h3);
            __syncthreads();
        }
    } else {
        h[0] = 0u; h[1] = 0u; h[2] = 0u; h[3] = 0u;       // self-clean
    }

    if (fb) {
        if (t == 0) g_ctl[CTL_FLAG] = 1u;
        __syncthreads();
        fb_path(locs, scores, anchors, A, B, sv, &s_nc, &s_T);
        return;
    }

    // sv[0..nc) is globally sorted desc; nc >= K_SEL
    for (int r = t; r < K_SEL; r += 1024) {
        unsigned long long v = sv[r];
        unsigned int key = (unsigned int)(v >> 32);
        unsigned int idx = ~(unsigned int)(v & 0xFFFFFFFFu);
        g_validk[r] = (key != 0u) ? 1 : 0;
        float4 box = make_float4(0.f, 0.f, 0.f, 0.f);
        if (key != 0u) box = decode_box(anchors[idx], locs[idx]);
        g_boxes[r] = box;
    }
}

// -------- K3: flat candidate-pair extraction (NO division, no smem) --------
__global__ void __launch_bounds__(256) k_pairs() {
    int ic = blockIdx.x;                 // 32 i's
    int jc = blockIdx.y;                 // 8 j's
    if (ic * 32 >= jc * 8 + 8) return;
    int lane = threadIdx.x & 31;
    int w    = threadIdx.x >> 5;
    int i = ic * 32 + lane;
    int j = jc * 8 + w;
    bool hit = false;
    if (i < j && j < K_SEL) {
        float4 ba = g_boxes[i];
        float4 bb = g_boxes[j];
        float xx1 = fmaxf(ba.x, bb.x);
        float yy1 = fmaxf(ba.y, bb.y);
        float xx2 = fminf(ba.z, bb.z);
        float yy2 = fminf(ba.w, bb.w);
        float iw = fmaxf(xx2 - xx1, 0.0f);
        float ih = fmaxf(yy2 - yy1, 0.0f);
        float inter = iw * ih;
        float ai = (ba.z - ba.x) * (ba.w - ba.y);
        float aj = (bb.z - bb.x) * (bb.w - bb.y);
        float u = fmaxf(ai + aj - inter, 1e-9f);
        hit = (inter > 0.699f * u);      // conservative, division-free
    }
    unsigned int mask = __ballot_sync(0xFFFFFFFFu, hit);
    if (mask) {
        int leader = __ffs(mask) - 1;
        unsigned int basep = 0;
        if (lane == leader)
            basep = atomicAdd(&g_ctl[CTL_NPAIRS], (unsigned)__popc(mask));
        basep = __shfl_sync(0xFFFFFFFFu, basep, leader);
        if (hit) {
            int rank = __popc(mask & ((1u << lane) - 1u));
            unsigned int pos = basep + rank;
            if (pos < (unsigned)PAIR_CAP)
                g_pairs[pos] = ((unsigned)i << 11) | (unsigned)j;
        }
    }
}

// -------- K4: exact verify + Jacobi greedy-NMS + compact + output ----------
__global__ void k_resolve(float* __restrict__ outf) {
    __shared__ unsigned char ka[K_SEL], kb[K_SEL];
    __shared__ int changed;
    __shared__ int psA[2048], psB[2048];
    int t = threadIdx.x;
    int np = (int)g_ctl[CTL_NPAIRS];
    if (np > PAIR_CAP) np = PAIR_CAP;

    // exact re-verification of candidates (divisions live here only)
    for (int p = t; p < np; p += 1024) {
        unsigned int pr = g_pairs[p];
        int i = (int)(pr >> 11), j = (int)(pr & 2047u);
        float4 ba = g_boxes[i];
        float4 bb = g_boxes[j];
        float xx1 = fmaxf(ba.x, bb.x);
        float yy1 = fmaxf(ba.y, bb.y);
        float xx2 = fminf(ba.z, bb.z);
        float yy2 = fminf(ba.w, bb.w);
        float iw = fmaxf(xx2 - xx1, 0.0f);
        float ih = fmaxf(yy2 - yy1, 0.0f);
        float inter = iw * ih;
        float ai = (ba.z - ba.x) * (ba.w - ba.y);
        float aj = (bb.z - bb.x) * (bb.w - bb.y);
        float u = fmaxf(ai + aj - inter, 1e-9f);
        if (!(inter / u > NMS_TH)) g_pairs[p] = 0xFFFFFFFFu;
    }
    __syncthreads();

    for (int j = t; j < K_SEL; j += 1024) ka[j] = g_validk[j];
    __syncthreads();
    for (int it = 0; it <= K_SEL; ++it) {
        if (t == 0) changed = 0;
        for (int j = t; j < K_SEL; j += 1024) kb[j] = g_validk[j];
        __syncthreads();
        for (int p = t; p < np; p += 1024) {
            unsigned int pr = g_pairs[p];
            if (pr == 0xFFFFFFFFu) continue;
            int i = (int)(pr >> 11), j = (int)(pr & 2047u);
            if (ka[i]) kb[j] = 0;
        }
        __syncthreads();
        for (int j = t; j < K_SEL; j += 1024) {
            if (kb[j] != ka[j]) { changed = 1; ka[j] = kb[j]; }
        }
        __syncthreads();
        int done = (changed == 0);
        __syncthreads();
        if (done) break;
    }
    for (int i = t; i < 2048; i += 1024) psA[i] = (i < K_SEL) ? (int)ka[i] : 0;
    __syncthreads();
    int* src = psA; int* dst = psB;
    for (int d = 1; d < 2048; d <<= 1) {
        for (int i = t; i < 2048; i += 1024)
            dst[i] = src[i] + (i >= d ? src[i - d] : 0);
        __syncthreads();
        int* t2 = src; src = dst; dst = t2;
    }
    float4* out4 = (float4*)outf;
    for (int r = t; r < OUT_ROWS; r += 1024)
        out4[r] = make_float4(0.f, 0.f, 0.f, 0.f);
    __syncthreads();
    for (int j = t; j < K_SEL; j += 1024) {
        if (ka[j]) {
            int pos = src[j] - 1;
            if (pos < OUT_ROWS) out4[pos] = g_boxes[j];
        }
    }
    __syncthreads();
    if (t < 16) g_ctl[t] = 0u;          // self-clean all control state
}

extern "C" void kernel_launch(void* const* d_in, const int* in_sizes, int n_in,
                              void* d_out, int out_size) {
    const float4* locs    = (const float4*)d_in[0];
    const float*  scores  = (const float*) d_in[1];
    const float4* scores4 = (const float4*)d_in[1];
    const float4* anchors = (const float4*)d_in[2];
    float* out = (float*)d_out;

    k_scan<<<977, 256>>>(locs, scores4, anchors);
    k_top<<<1, 1024>>>(locs, scores, anchors);
    k_pairs<<<dim3(PAIR_GX, PAIR_GY), 256>>>();
    k_resolve<<<1, 1024>>>(out);
}